// round 4
// baseline (speedup 1.0000x reference)
#include <cuda_runtime.h>

// PatchShuffle: RATIO=0.75, NUM_ROWS=16, NUM_COLS=64, T=1024, B=64, C=768, STRIPE_W=48
// Output layout (flat fp32):
//   visible [12,582,912] | fwd [65,536] | bwd [65,536] | stripe_bounds [128]

#define NCOLS    64
#define BATCH    64
#define SW       48
#define NVIS     16
#define ROW_F4   192            // float4 per (t,b) row
#define VIS_ELEMS 12582912LL
#define NWARPS_TOT 8192u        // 16384 output rows / 2 rows per warp
#define NBLOCKS   1024u         // NWARPS_TOT / 8 warps per block

__device__ __forceinline__ int perm_of(int j, int s) {
    return (j < NVIS) ? ((j < s) ? j : j + SW) : (s + (j - NVIS));
}

__global__ void __launch_bounds__(256)
patch_shuffle_fused(const float4* __restrict__ patches,
                    const int*    __restrict__ start_cols,
                    float*        __restrict__ out) {
    const unsigned tid = threadIdx.x;
    const unsigned blk = blockIdx.x;

    // ---- index outputs, folded into the gather blocks (issued first so the
    //      stores hide under the gather's load latency) ----
    if (tid < 128) {
        unsigned k = blk * 128 + tid;          // covers [0, 131072) exactly
        if (k < 65536) {
            // fwd[t, b]
            int b = k & 63;
            int t = k >> 6;
            int j = t & 63, r = t >> 6;
            int s = __ldg(&start_cols[b]);
            out[VIS_ELEMS + k] = (float)(r * NCOLS + perm_of(j, s));
        } else {
            // bwd[p, b] (closed-form inverse)
            unsigned m = k - 65536;
            int b = m & 63;
            int p = m >> 6;
            int c = p & 63, r = p >> 6;
            int s = __ldg(&start_cols[b]);
            int inv = (c < s) ? c : ((c < s + SW) ? (NVIS + c - s) : (c - SW));
            out[VIS_ELEMS + 65536 + m] = (float)(r * NCOLS + inv);
        }
    } else if (blk == 0) {
        // stripe_bounds: 128 elems, row 0 = start, row 1 = start + SW
        unsigned m = tid - 128;
        int b = m & 63;
        int s = __ldg(&start_cols[b]);
        out[VIS_ELEMS + 131072 + m] = (float)((m < 64) ? s : s + SW);
    }

    // ---- gather: each warp moves two output rows (w and w + 8192) ----
    unsigned w = blk * 8 + (tid >> 5);         // [0, 8192)
    int lane = tid & 31;
    int b = w & 63;
    int t0 = w >> 6;                           // [0, 128)
    int j  = t0 & 63;
    int r0 = t0 >> 6;                          // [0, 2)
    int s  = __ldg(&start_cols[b]);
    int src_t0 = r0 * NCOLS + perm_of(j, s);
    int src_t1 = src_t0 + 128;                 // t1 = t0 + 128 -> r + 2, same j

    const float4* sp0 = patches + ((long)src_t0 * BATCH + b) * ROW_F4 + lane;
    const float4* sp1 = patches + ((long)src_t1 * BATCH + b) * ROW_F4 + lane;
    float4* dp0 = (float4*)out + (long)w * ROW_F4 + lane;
    float4* dp1 = (float4*)out + (long)(w + NWARPS_TOT) * ROW_F4 + lane;

    float4 v[12];
#pragma unroll
    for (int i = 0; i < 6; i++) v[i]     = sp0[i * 32];
#pragma unroll
    for (int i = 0; i < 6; i++) v[6 + i] = sp1[i * 32];
#pragma unroll
    for (int i = 0; i < 6; i++) dp0[i * 32] = v[i];
#pragma unroll
    for (int i = 0; i < 6; i++) dp1[i * 32] = v[6 + i];
}

extern "C" void kernel_launch(void* const* d_in, const int* in_sizes, int n_in,
                              void* d_out, int out_size) {
    const float4* patches    = (const float4*)d_in[0];
    const int*    start_cols = (const int*)d_in[1];
    float*        out        = (float*)d_out;

    patch_shuffle_fused<<<NBLOCKS, 256>>>(patches, start_cols, out);
}

// round 5
// speedup vs baseline: 1.1544x; 1.1544x over previous
#include <cuda_runtime.h>

// PatchShuffle: RATIO=0.75, NUM_ROWS=16, NUM_COLS=64, T=1024, B=64, C=768, STRIPE_W=48
// Output layout (flat fp32):
//   visible [12,582,912] | fwd [65,536] | bwd [65,536] | stripe_bounds [128]

#define NCOLS    64
#define BATCH    64
#define SW       48
#define NVIS     16
#define ROW_F4   192           // float4 per (t,b) row
#define VIS_ELEMS 12582912LL
#define GATHER_BLOCKS 2048u    // 16384 rows / 8 warps per block
#define IDX_WORK 131200u
#define IDX_BLOCKS 513u

__device__ __forceinline__ int perm_of(int j, int s) {
    return (j < NVIS) ? ((j < s) ? j : j + SW) : (s + (j - NVIS));
}

__global__ void __launch_bounds__(256)
patch_shuffle_fused(const float4* __restrict__ patches,
                    const int*    __restrict__ start_cols,
                    float*        __restrict__ out) {
    if (blockIdx.x < GATHER_BLOCKS) {
        // ---- gather: one warp per output row; 6 front-batched LDG.128 ----
        unsigned warp = blockIdx.x * 8 + (threadIdx.x >> 5);
        int lane = threadIdx.x & 31;
        int b = warp & 63;
        int t = warp >> 6;              // t in [0,256)
        int j = t & 63;
        int r = t >> 6;
        int s = __ldg(&start_cols[b]);
        int src_t = r * NCOLS + perm_of(j, s);

        const float4* src = patches + ((long)src_t * BATCH + b) * ROW_F4 + lane;
        float4*       dst = (float4*)out + (long)warp * ROW_F4 + lane;

        float4 v0 = src[0];
        float4 v1 = src[32];
        float4 v2 = src[64];
        float4 v3 = src[96];
        float4 v4 = src[128];
        float4 v5 = src[160];
        // streaming stores: evict-first so the input stays L2-resident
        __stcs(&dst[0],   v0);
        __stcs(&dst[32],  v1);
        __stcs(&dst[64],  v2);
        __stcs(&dst[96],  v3);
        __stcs(&dst[128], v4);
        __stcs(&dst[160], v5);
        return;
    }

    // ---- index outputs: thread-per-element tail blocks ----
    unsigned k = (blockIdx.x - GATHER_BLOCKS) * blockDim.x + threadIdx.x;
    if (k >= IDX_WORK) return;

    if (k < 65536) {
        // fwd[t, b]
        int b = k & 63;
        int t = k >> 6;
        int j = t & 63, r = t >> 6;
        int s = __ldg(&start_cols[b]);
        out[VIS_ELEMS + k] = (float)(r * NCOLS + perm_of(j, s));
    } else if (k < 131072) {
        // bwd[p, b] (closed-form inverse)
        unsigned m = k - 65536;
        int b = m & 63;
        int p = m >> 6;
        int c = p & 63, r = p >> 6;
        int s = __ldg(&start_cols[b]);
        int inv = (c < s) ? c : ((c < s + SW) ? (NVIS + c - s) : (c - SW));
        out[VIS_ELEMS + 65536 + m] = (float)(r * NCOLS + inv);
    } else {
        unsigned m = k - 131072;
        int b = m & 63;
        int s = __ldg(&start_cols[b]);
        out[VIS_ELEMS + 131072 + m] = (float)((m < 64) ? s : s + SW);
    }
}

extern "C" void kernel_launch(void* const* d_in, const int* in_sizes, int n_in,
                              void* d_out, int out_size) {
    const float4* patches    = (const float4*)d_in[0];
    const int*    start_cols = (const int*)d_in[1];
    float*        out        = (float*)d_out;

    patch_shuffle_fused<<<GATHER_BLOCKS + IDX_BLOCKS, 256>>>(
        patches, start_cols, out);
}

// round 6
// speedup vs baseline: 1.1572x; 1.0025x over previous
#include <cuda_runtime.h>

// PatchShuffle: RATIO=0.75, NUM_ROWS=16, NUM_COLS=64, T=1024, B=64, C=768, STRIPE_W=48
// Output layout (flat fp32):
//   visible [12,582,912] | fwd [65,536] | bwd [65,536] | stripe_bounds [128]

#define NCOLS    64
#define BATCH    64
#define SW       48
#define NVIS     16
#define ROW_F4   192           // float4 per (t,b) row
#define VIS_ELEMS 12582912LL
#define NBLOCKS  2048u         // 16384 rows / 8 warps per block

__device__ __forceinline__ int perm_of(int j, int s) {
    return (j < NVIS) ? ((j < s) ? j : j + SW) : (s + (j - NVIS));
}

__global__ void __launch_bounds__(256)
patch_shuffle_fused(const float4* __restrict__ patches,
                    const int*    __restrict__ start_cols,
                    float*        __restrict__ out) {
    const unsigned tid = threadIdx.x;
    const unsigned blk = blockIdx.x;

    // ---- index outputs folded into gather blocks: 64 elems per block ----
    if (tid < 64) {
        unsigned k = blk * 64 + tid;           // covers [0, 131072) exactly
        if (k < 65536) {
            // fwd[t, b]
            int b = k & 63;
            int t = k >> 6;
            int j = t & 63, r = t >> 6;
            int s = __ldg(&start_cols[b]);
            __stcs(&out[VIS_ELEMS + k], (float)(r * NCOLS + perm_of(j, s)));
        } else {
            // bwd[p, b] (closed-form inverse)
            unsigned m = k - 65536;
            int b = m & 63;
            int p = m >> 6;
            int c = p & 63, r = p >> 6;
            int s = __ldg(&start_cols[b]);
            int inv = (c < s) ? c : ((c < s + SW) ? (NVIS + c - s) : (c - SW));
            __stcs(&out[VIS_ELEMS + 65536 + m], (float)(r * NCOLS + inv));
        }
    } else if (blk == 0 && tid < 192) {
        // stripe_bounds: 128 elems, row 0 = start, row 1 = start + SW
        unsigned m = tid - 64;
        int b = m & 63;
        int s = __ldg(&start_cols[b]);
        __stcs(&out[VIS_ELEMS + 131072 + m], (float)((m < 64) ? s : s + SW));
    }

    // ---- gather: one warp per output row; 6 front-batched LDG.128 ----
    unsigned warp = blk * 8 + (tid >> 5);
    int lane = tid & 31;
    int b = warp & 63;
    int t = warp >> 6;                         // t in [0,256)
    int j = t & 63;
    int r = t >> 6;
    int s = __ldg(&start_cols[b]);
    int src_t = r * NCOLS + perm_of(j, s);

    const float4* src = patches + ((long)src_t * BATCH + b) * ROW_F4 + lane;
    float4*       dst = (float4*)out + (long)warp * ROW_F4 + lane;

    float4 v0 = src[0];
    float4 v1 = src[32];
    float4 v2 = src[64];
    float4 v3 = src[96];
    float4 v4 = src[128];
    float4 v5 = src[160];
    // streaming stores: evict-first so the input stays L2-resident across replays
    __stcs(&dst[0],   v0);
    __stcs(&dst[32],  v1);
    __stcs(&dst[64],  v2);
    __stcs(&dst[96],  v3);
    __stcs(&dst[128], v4);
    __stcs(&dst[160], v5);
}

extern "C" void kernel_launch(void* const* d_in, const int* in_sizes, int n_in,
                              void* d_out, int out_size) {
    const float4* patches    = (const float4*)d_in[0];
    const int*    start_cols = (const int*)d_in[1];
    float*        out        = (float*)d_out;

    patch_shuffle_fused<<<NBLOCKS, 256>>>(patches, start_cols, out);
}